// round 16
// baseline (speedup 1.0000x reference)
#include <cuda_runtime.h>
#include <cuda_bf16.h>
#include <cstdint>

#define N_NODES 100000
#define N_EDGES 1600000
#define D 64
#define N_GRAPHS 16
#define N_CLASSES 6
#define BN_EPS 1e-5f
#define MAXDEG 64   // Poisson(16): max over 100K nodes ~35; P(any >= 64) < 1e-15

#define NPB 128

// ---------------- device scratch (no allocation allowed) ----------------
__device__ __align__(16) float g_h[2][N_NODES * D];        // fp32 layer buffers
__device__ __align__(16) __nv_bfloat16 g_hb[2][N_NODES * D]; // bf16 mirrors
__device__ __align__(16) __nv_bfloat16 g_xb[N_NODES * D];    // bf16 mirror of x
__device__ __align__(16) float g_z[N_NODES * D];           // gathered z
__device__ int g_deg[N_NODES];                             // degree (atomic cursor)
__device__ __align__(16) int g_srcs[N_NODES * MAXDEG];     // padded CSR
__device__ float g_pool[N_GRAPHS * D];
__device__ float g_cnt[N_GRAPHS];

// ---------------- packed f32x2 helpers (FFMA2: 2x FP32 FMA rate) ----------
__device__ __forceinline__ unsigned long long pack2(float lo, float hi) {
    unsigned long long r;
    asm("mov.b64 %0, {%1, %2};" : "=l"(r) : "f"(lo), "f"(hi));
    return r;
}
__device__ __forceinline__ void unpack2(float& lo, float& hi, unsigned long long v) {
    asm("mov.b64 {%0, %1}, %2;" : "=f"(lo), "=f"(hi) : "l"(v));
}
__device__ __forceinline__ void fma2(unsigned long long& d,
                                     unsigned long long a, unsigned long long b) {
    asm("fma.rn.f32x2 %0, %1, %2, %3;" : "=l"(d) : "l"(a), "l"(b), "l"(d));
}

// add 4 bf16 (one 8B word) into float4 acc
__device__ __forceinline__ void acc_bf4(float4& acc, unsigned long long raw) {
    __nv_bfloat162 p0 = reinterpret_cast<const __nv_bfloat162*>(&raw)[0];
    __nv_bfloat162 p1 = reinterpret_cast<const __nv_bfloat162*>(&raw)[1];
    float2 f0 = __bfloat1622float2(p0);
    float2 f1 = __bfloat1622float2(p1);
    acc.x += f0.x; acc.y += f0.y; acc.z += f1.x; acc.w += f1.y;
}

// ---------------- prep: zero cursors + pool ----------------
__global__ void prep_kernel() {
    int i = blockIdx.x * blockDim.x + threadIdx.x;
    int stride = gridDim.x * blockDim.x;
    for (int n = i; n < N_NODES; n += stride) g_deg[n] = 0;
    if (i < N_GRAPHS * D) g_pool[i] = 0.f;
    if (i < N_GRAPHS) g_cnt[i] = 0.f;
}

// ---------------- x -> bf16 mirror (once per call) ----------------
__global__ __launch_bounds__(256) void cvt_kernel(const float* __restrict__ x) {
    int t = blockIdx.x * 256 + threadIdx.x;         // one thread = 8 elems
    if (t >= N_NODES * D / 8) return;
    float4 a = __ldg(reinterpret_cast<const float4*>(x) + t * 2);
    float4 b = __ldg(reinterpret_cast<const float4*>(x) + t * 2 + 1);
    __nv_bfloat162 r[4];
    r[0] = __floats2bfloat162_rn(a.x, a.y);
    r[1] = __floats2bfloat162_rn(a.z, a.w);
    r[2] = __floats2bfloat162_rn(b.x, b.y);
    r[3] = __floats2bfloat162_rn(b.z, b.w);
    *reinterpret_cast<uint4*>(g_xb + (size_t)t * 8) = *reinterpret_cast<uint4*>(r);
}

// ---------------- padded-CSR build: one pass, 4 edges/thread (int4) --------
__global__ __launch_bounds__(256) void place_kernel(const int* __restrict__ ei) {
    int t = blockIdx.x * 256 + threadIdx.x;
    if (t >= N_EDGES / 4) return;
    int4 s4 = __ldg(reinterpret_cast<const int4*>(ei) + t);
    int4 d4 = __ldg(reinterpret_cast<const int4*>(ei + N_EDGES) + t);
    int ss[4] = {s4.x, s4.y, s4.z, s4.w};
    int dd[4] = {d4.x, d4.y, d4.z, d4.w};
    #pragma unroll
    for (int q = 0; q < 4; ++q) {
        unsigned s = (unsigned)ss[q], d = (unsigned)dd[q];
        if (s < (unsigned)N_NODES && d < (unsigned)N_NODES) {
            int pos = atomicAdd(&g_deg[d], 1);
            if (pos < MAXDEG) g_srcs[d * MAXDEG + pos] = (int)s;
        }
    }
}

// ---------------- gather: z[n] = h_fp32[n] + sum bf16 h[s] -----------------
__global__ __launch_bounds__(256, 6) void gather_kernel(
    const float* __restrict__ x, int in_sel)
{
    const float* __restrict__ hin = (in_sel < 0) ? x : g_h[in_sel];
    const __nv_bfloat16* __restrict__ hb = (in_sel < 0) ? g_xb : g_hb[in_sel];
    const float4* __restrict__ h4 = reinterpret_cast<const float4*>(hin);
    unsigned t = blockIdx.x * 256u + threadIdx.x;
    if (t >= (unsigned)N_NODES * 16u) return;
    unsigned n = t >> 4;
    unsigned c = t & 15u;

    float4 acc = __ldg(h4 + (size_t)n * 16 + c);   // self term (fp32)
    int deg = min(__ldg(&g_deg[n]), MAXDEG);
    const int4* __restrict__ sp4 = reinterpret_cast<const int4*>(g_srcs + (size_t)n * MAXDEG);

    int e = 0;
    for (; e + 4 <= deg; e += 4) {
        int4 s = __ldg(sp4 + (e >> 2));
        unsigned long long r0 = __ldg(reinterpret_cast<const unsigned long long*>(
            hb + (size_t)s.x * D + c * 4));
        unsigned long long r1 = __ldg(reinterpret_cast<const unsigned long long*>(
            hb + (size_t)s.y * D + c * 4));
        unsigned long long r2 = __ldg(reinterpret_cast<const unsigned long long*>(
            hb + (size_t)s.z * D + c * 4));
        unsigned long long r3 = __ldg(reinterpret_cast<const unsigned long long*>(
            hb + (size_t)s.w * D + c * 4));
        acc_bf4(acc, r0); acc_bf4(acc, r1); acc_bf4(acc, r2); acc_bf4(acc, r3);
    }
    const int* __restrict__ sp = g_srcs + (size_t)n * MAXDEG;
    for (; e < deg; ++e) {
        int s = __ldg(sp + e);
        unsigned long long r = __ldg(reinterpret_cast<const unsigned long long*>(
            hb + (size_t)s * D + c * 4));
        acc_bf4(acc, r);
    }
    reinterpret_cast<float4*>(g_z)[(size_t)n * 16 + c] = acc;
}

// ---------------- MLP kernel: 8 nodes x 8 outs thread tile -----------------
// 128 threads per 128-node tile, 4 blocks/SM (128-reg cap).
// Per k-iter: 2 z-LDS.128 + 2 w-LDS.128 + 8 dup MOVs + 32 FFMA2 = 44 issues
// per 64 MACs (0.69/MAC) and 1.5 LDS-bytes/MAC (vs 0.84 / 2.5 in the 8x4 tile).
#define ZT_LD 132
#define MLP_SMEM_FLOATS (D * ZT_LD + D * D + 4 * D)  // 12800 floats = 51.2KB

__global__ __launch_bounds__(128, 4) void mlp_kernel(
    int out_sel, int layer, int write_bf16,
    const float* __restrict__ W1, const float* __restrict__ b1,
    const float* __restrict__ g1, const float* __restrict__ be1,
    const float* __restrict__ m1, const float* __restrict__ v1,
    const float* __restrict__ W2, const float* __restrict__ b2,
    const float* __restrict__ g2, const float* __restrict__ be2,
    const float* __restrict__ m2, const float* __restrict__ v2)
{
    extern __shared__ float smem[];
    float* zt  = smem;                    // [64][132] transposed activations
    float* Wb  = smem + D * ZT_LD;        // [64][64] current weight
    float* sc1 = Wb + D * D;
    float* sh1 = sc1 + D;
    float* sc2 = sh1 + D;
    float* sh2 = sc2 + D;

    const int tid = threadIdx.x;
    const int node0 = blockIdx.x * NPB;
    float* __restrict__ hout = g_h[out_sel];
    __nv_bfloat16* __restrict__ hbout = g_hb[out_sel];
    const float4* __restrict__ z4 = reinterpret_cast<const float4*>(g_z);

    // stage W1 + folded BN params
    const float* w1 = W1 + layer * D * D;
    #pragma unroll
    for (int i = tid; i < D * D; i += 128) Wb[i] = __ldg(w1 + i);
    if (tid < D) {
        int o = layer * D + tid;
        float s1 = __ldg(g1 + o) * rsqrtf(__ldg(v1 + o) + BN_EPS);
        sc1[tid] = s1;
        sh1[tid] = (__ldg(b1 + o) - __ldg(m1 + o)) * s1 + __ldg(be1 + o);
        float s2 = __ldg(g2 + o) * rsqrtf(__ldg(v2 + o) + BN_EPS);
        sc2[tid] = s2;
        sh2[tid] = (__ldg(b2 + o) - __ldg(m2 + o)) * s2 + __ldg(be2 + o);
    }

    // stage z transposed: task = (local node, chunk)
    #pragma unroll
    for (int it = 0; it < (NPB * 16) / 128; ++it) {
        int task = tid + it * 128;
        int nl = task >> 4;
        int c  = task & 15;
        int n  = node0 + nl;
        if (n < N_NODES) {
            float4 v = __ldg(z4 + (size_t)n * 16 + c);
            int k = c * 4;
            zt[(k + 0) * ZT_LD + nl] = v.x;
            zt[(k + 1) * ZT_LD + nl] = v.y;
            zt[(k + 2) * ZT_LD + nl] = v.z;
            zt[(k + 3) * ZT_LD + nl] = v.w;
        }
    }
    __syncthreads();

    // ---- GEMM thread tile: 8 nodes (4 f32x2 pairs) x 8 outs ----
    const int tj = tid & 7;       // out group: j0 = 8*tj
    const int tn = tid >> 3;      // node group: n0 = 8*tn
    const int j0 = tj * 8;
    const int n0 = tn * 8;

    unsigned long long acc[4][8];   // [node pair][out j]
    #pragma unroll
    for (int p = 0; p < 4; ++p)
        #pragma unroll
        for (int j = 0; j < 8; ++j) acc[p][j] = 0ull;

    // GEMM1: z @ W1
    #pragma unroll 2
    for (int k = 0; k < D; ++k) {
        ulonglong2 za = *reinterpret_cast<const ulonglong2*>(zt + k * ZT_LD + n0);
        ulonglong2 zb = *reinterpret_cast<const ulonglong2*>(zt + k * ZT_LD + n0 + 4);
        float4 wlo = *reinterpret_cast<const float4*>(Wb + k * D + j0);
        float4 whi = *reinterpret_cast<const float4*>(Wb + k * D + j0 + 4);
        unsigned long long wd[8];
        wd[0] = pack2(wlo.x, wlo.x); wd[1] = pack2(wlo.y, wlo.y);
        wd[2] = pack2(wlo.z, wlo.z); wd[3] = pack2(wlo.w, wlo.w);
        wd[4] = pack2(whi.x, whi.x); wd[5] = pack2(whi.y, whi.y);
        wd[6] = pack2(whi.z, whi.z); wd[7] = pack2(whi.w, whi.w);
        unsigned long long zp[4] = {za.x, za.y, zb.x, zb.y};
        #pragma unroll
        for (int p = 0; p < 4; ++p)
            #pragma unroll
            for (int j = 0; j < 8; ++j)
                fma2(acc[p][j], zp[p], wd[j]);
    }
    __syncthreads();

    // BN1 + ReLU -> y back into zt (packed 8B stores); swap W2 into Wb
    {
        float s_[8], t_[8];
        #pragma unroll
        for (int j = 0; j < 8; ++j) { s_[j] = sc1[j0 + j]; t_[j] = sh1[j0 + j]; }
        #pragma unroll
        for (int p = 0; p < 4; ++p)
            #pragma unroll
            for (int j = 0; j < 8; ++j) {
                float lo, hi;
                unpack2(lo, hi, acc[p][j]);
                lo = fmaxf(fmaf(lo, s_[j], t_[j]), 0.f);
                hi = fmaxf(fmaf(hi, s_[j], t_[j]), 0.f);
                *reinterpret_cast<unsigned long long*>(
                    zt + (j0 + j) * ZT_LD + n0 + 2 * p) = pack2(lo, hi);
            }
    }
    const float* w2 = W2 + layer * D * D;
    #pragma unroll
    for (int i = tid; i < D * D; i += 128) Wb[i] = __ldg(w2 + i);
    __syncthreads();

    // GEMM2: y @ W2
    #pragma unroll
    for (int p = 0; p < 4; ++p)
        #pragma unroll
        for (int j = 0; j < 8; ++j) acc[p][j] = 0ull;

    #pragma unroll 2
    for (int k = 0; k < D; ++k) {
        ulonglong2 ya = *reinterpret_cast<const ulonglong2*>(zt + k * ZT_LD + n0);
        ulonglong2 yb = *reinterpret_cast<const ulonglong2*>(zt + k * ZT_LD + n0 + 4);
        float4 wlo = *reinterpret_cast<const float4*>(Wb + k * D + j0);
        float4 whi = *reinterpret_cast<const float4*>(Wb + k * D + j0 + 4);
        unsigned long long wd[8];
        wd[0] = pack2(wlo.x, wlo.x); wd[1] = pack2(wlo.y, wlo.y);
        wd[2] = pack2(wlo.z, wlo.z); wd[3] = pack2(wlo.w, wlo.w);
        wd[4] = pack2(whi.x, whi.x); wd[5] = pack2(whi.y, whi.y);
        wd[6] = pack2(whi.z, whi.z); wd[7] = pack2(whi.w, whi.w);
        unsigned long long yp[4] = {ya.x, ya.y, yb.x, yb.y};
        #pragma unroll
        for (int p = 0; p < 4; ++p)
            #pragma unroll
            for (int j = 0; j < 8; ++j)
                fma2(acc[p][j], yp[p], wd[j]);
    }

    // BN2 + ReLU, coalesced fp32 stores + optional bf16 mirror
    {
        float s_[8], t_[8];
        #pragma unroll
        for (int j = 0; j < 8; ++j) { s_[j] = sc2[j0 + j]; t_[j] = sh2[j0 + j]; }
        #pragma unroll
        for (int p = 0; p < 4; ++p) {
            float lo[8], hi[8];
            #pragma unroll
            for (int j = 0; j < 8; ++j) {
                float a, b;
                unpack2(a, b, acc[p][j]);
                lo[j] = fmaxf(fmaf(a, s_[j], t_[j]), 0.f);
                hi[j] = fmaxf(fmaf(b, s_[j], t_[j]), 0.f);
            }
            int na = node0 + n0 + 2 * p;
            int nb = na + 1;
            if (na < N_NODES) {
                *reinterpret_cast<float4*>(hout + (size_t)na * D + j0) =
                    make_float4(lo[0], lo[1], lo[2], lo[3]);
                *reinterpret_cast<float4*>(hout + (size_t)na * D + j0 + 4) =
                    make_float4(lo[4], lo[5], lo[6], lo[7]);
                if (write_bf16) {
                    __nv_bfloat162 r[4];
                    r[0] = __floats2bfloat162_rn(lo[0], lo[1]);
                    r[1] = __floats2bfloat162_rn(lo[2], lo[3]);
                    r[2] = __floats2bfloat162_rn(lo[4], lo[5]);
                    r[3] = __floats2bfloat162_rn(lo[6], lo[7]);
                    *reinterpret_cast<uint4*>(hbout + (size_t)na * D + j0) =
                        *reinterpret_cast<uint4*>(r);
                }
            }
            if (nb < N_NODES) {
                *reinterpret_cast<float4*>(hout + (size_t)nb * D + j0) =
                    make_float4(hi[0], hi[1], hi[2], hi[3]);
                *reinterpret_cast<float4*>(hout + (size_t)nb * D + j0 + 4) =
                    make_float4(hi[4], hi[5], hi[6], hi[7]);
                if (write_bf16) {
                    __nv_bfloat162 r[4];
                    r[0] = __floats2bfloat162_rn(hi[0], hi[1]);
                    r[1] = __floats2bfloat162_rn(hi[2], hi[3]);
                    r[2] = __floats2bfloat162_rn(hi[4], hi[5]);
                    r[3] = __floats2bfloat162_rn(hi[6], hi[7]);
                    *reinterpret_cast<uint4*>(hbout + (size_t)nb * D + j0) =
                        *reinterpret_cast<uint4*>(r);
                }
            }
        }
    }
}

// ---------------- global mean pool (batch is sorted int32) ----------------
#define POOL_BLOCKS 512
__global__ __launch_bounds__(256) void pool_kernel(const int* __restrict__ batch, int sel) {
    const float* __restrict__ h = g_h[sel];
    int d = threadIdx.x & 63;
    int row = blockIdx.x * 4 + (threadIdx.x >> 6);
    int total_rows = POOL_BLOCKS * 4;
    int chunk = (N_NODES + total_rows - 1) / total_rows;
    int start = row * chunk;
    int end = min(start + chunk, N_NODES);
    if (start >= end) return;
    int cur = __ldg(batch + start);
    float acc = 0.f, cnt = 0.f;
    for (int n = start; n < end; ++n) {
        int b = __ldg(batch + n);
        if (b != cur) {
            if ((unsigned)cur < N_GRAPHS) {
                atomicAdd(&g_pool[cur * D + d], acc);
                if (d == 0) atomicAdd(&g_cnt[cur], cnt);
            }
            acc = 0.f; cnt = 0.f; cur = b;
        }
        acc += __ldg(h + (size_t)n * D + d);
        cnt += 1.f;
    }
    if ((unsigned)cur < N_GRAPHS) {
        atomicAdd(&g_pool[cur * D + d], acc);
        if (d == 0) atomicAdd(&g_cnt[cur], cnt);
    }
}

// ---------------- heads: out = [primary(16x6), secondary(16x6)] ----------------
__global__ void head_kernel(const float* __restrict__ wp, const float* __restrict__ bp,
                            const float* __restrict__ ws, const float* __restrict__ bs,
                            float* __restrict__ out) {
    int t = threadIdx.x;
    if (t >= N_GRAPHS * N_CLASSES) return;
    int g = t / N_CLASSES, c = t % N_CLASSES;
    float inv = 1.f / fmaxf(g_cnt[g], 1.f);
    float accP = 0.f, accS = 0.f;
    #pragma unroll
    for (int d = 0; d < D; ++d) {
        float p = g_pool[g * D + d] * inv;
        accP = fmaf(p, wp[d * N_CLASSES + c], accP);
        accS = fmaf(p, ws[d * N_CLASSES + c], accS);
    }
    out[g * N_CLASSES + c] = accP + bp[c];
    out[N_GRAPHS * N_CLASSES + g * N_CLASSES + c] = accS + bs[c];
}

// ---------------- launch ----------------
extern "C" void kernel_launch(void* const* d_in, const int* in_sizes, int n_in,
                              void* d_out, int out_size) {
    const float* x   = (const float*)d_in[0];
    const int*   ei  = (const int*)d_in[1];    // int32 (JAX x64 disabled)
    const int*   bat = (const int*)d_in[2];    // int32
    const float* W1  = (const float*)d_in[3];
    const float* b1  = (const float*)d_in[4];
    const float* g1  = (const float*)d_in[5];
    const float* be1 = (const float*)d_in[6];
    const float* m1  = (const float*)d_in[7];
    const float* v1  = (const float*)d_in[8];
    const float* W2  = (const float*)d_in[9];
    const float* b2  = (const float*)d_in[10];
    const float* g2  = (const float*)d_in[11];
    const float* be2 = (const float*)d_in[12];
    const float* m2  = (const float*)d_in[13];
    const float* v2  = (const float*)d_in[14];
    const float* wp  = (const float*)d_in[15];
    const float* bp  = (const float*)d_in[16];
    const float* ws  = (const float*)d_in[17];
    const float* bs  = (const float*)d_in[18];
    float* out = (float*)d_out;

    const size_t mlp_smem = MLP_SMEM_FLOATS * sizeof(float);  // 51.2 KB
    cudaFuncSetAttribute(mlp_kernel, cudaFuncAttributeMaxDynamicSharedMemorySize,
                         (int)mlp_smem);

    // prep: cursors, pool, bf16 mirror of x, padded CSR
    prep_kernel<<<512, 256>>>();
    cvt_kernel<<<(N_NODES * D / 8 + 255) / 256, 256>>>(x);
    place_kernel<<<(N_EDGES / 4 + 255) / 256, 256>>>(ei);

    const int gather_grid = (N_NODES * 16 + 255) / 256;
    const int mlp_grid = (N_NODES + NPB - 1) / NPB;

    gather_kernel<<<gather_grid, 256>>>(x, -1);
    mlp_kernel<<<mlp_grid, 128, mlp_smem>>>(0, 0, 1,
        W1, b1, g1, be1, m1, v1, W2, b2, g2, be2, m2, v2);
    gather_kernel<<<gather_grid, 256>>>(x, 0);
    mlp_kernel<<<mlp_grid, 128, mlp_smem>>>(1, 1, 1,
        W1, b1, g1, be1, m1, v1, W2, b2, g2, be2, m2, v2);
    gather_kernel<<<gather_grid, 256>>>(x, 1);
    mlp_kernel<<<mlp_grid, 128, mlp_smem>>>(0, 2, 0,   // last layer: no mirror
        W1, b1, g1, be1, m1, v1, W2, b2, g2, be2, m2, v2);

    pool_kernel<<<POOL_BLOCKS, 256>>>(bat, 0);
    head_kernel<<<1, 128>>>(wp, bp, ws, bs, out);
}

// round 17
// speedup vs baseline: 1.1027x; 1.1027x over previous
#include <cuda_runtime.h>
#include <cuda_bf16.h>
#include <cstdint>

#define N_NODES 100000
#define N_EDGES 1600000
#define D 64
#define N_GRAPHS 16
#define N_CLASSES 6
#define BN_EPS 1e-5f
#define MAXDEG 64   // Poisson(16): max over 100K nodes ~35; P(any >= 64) < 1e-15

#define NPB 128

// ---------------- device scratch (no allocation allowed) ----------------
__device__ __align__(16) float g_h[2][N_NODES * D];        // fp32 layer buffers
__device__ __align__(16) __nv_bfloat16 g_hb[2][N_NODES * D]; // bf16 mirrors
__device__ __align__(16) __nv_bfloat16 g_xb[N_NODES * D];    // bf16 mirror of x
__device__ __align__(16) float g_z[N_NODES * D];           // gathered z
__device__ int g_deg[N_NODES];                             // degree (atomic cursor)
__device__ __align__(16) int g_srcs[N_NODES * MAXDEG];     // padded CSR
__device__ float g_pool[N_GRAPHS * D];
__device__ float g_cnt[N_GRAPHS];

// ---------------- packed f32x2 helpers (FFMA2: 2x FP32 FMA rate) ----------
__device__ __forceinline__ unsigned long long pack2(float lo, float hi) {
    unsigned long long r;
    asm("mov.b64 %0, {%1, %2};" : "=l"(r) : "f"(lo), "f"(hi));
    return r;
}
__device__ __forceinline__ void unpack2(float& lo, float& hi, unsigned long long v) {
    asm("mov.b64 {%0, %1}, %2;" : "=f"(lo), "=f"(hi) : "l"(v));
}
__device__ __forceinline__ void fma2(unsigned long long& d,
                                     unsigned long long a, unsigned long long b) {
    asm("fma.rn.f32x2 %0, %1, %2, %3;" : "=l"(d) : "l"(a), "l"(b), "l"(d));
}

// add 4 bf16 (one 8B word) into float4 acc
__device__ __forceinline__ void acc_bf4(float4& acc, unsigned long long raw) {
    __nv_bfloat162 p0 = reinterpret_cast<const __nv_bfloat162*>(&raw)[0];
    __nv_bfloat162 p1 = reinterpret_cast<const __nv_bfloat162*>(&raw)[1];
    float2 f0 = __bfloat1622float2(p0);
    float2 f1 = __bfloat1622float2(p1);
    acc.x += f0.x; acc.y += f0.y; acc.z += f1.x; acc.w += f1.y;
}

// ---------------- prep: zero cursors/pool + bf16 mirror of x (merged) ------
__global__ __launch_bounds__(256) void prep_kernel(const float* __restrict__ x) {
    int i = blockIdx.x * blockDim.x + threadIdx.x;
    int stride = gridDim.x * blockDim.x;
    for (int n = i; n < N_NODES; n += stride) g_deg[n] = 0;
    if (i < N_GRAPHS * D) g_pool[i] = 0.f;
    if (i < N_GRAPHS) g_cnt[i] = 0.f;
    for (int t = i; t < N_NODES * D / 8; t += stride) {
        float4 a = __ldg(reinterpret_cast<const float4*>(x) + t * 2);
        float4 b = __ldg(reinterpret_cast<const float4*>(x) + t * 2 + 1);
        __nv_bfloat162 r[4];
        r[0] = __floats2bfloat162_rn(a.x, a.y);
        r[1] = __floats2bfloat162_rn(a.z, a.w);
        r[2] = __floats2bfloat162_rn(b.x, b.y);
        r[3] = __floats2bfloat162_rn(b.z, b.w);
        *reinterpret_cast<uint4*>(g_xb + (size_t)t * 8) = *reinterpret_cast<uint4*>(r);
    }
}

// ---------------- padded-CSR build: one pass, 4 edges/thread (int4) --------
__global__ __launch_bounds__(256) void place_kernel(const int* __restrict__ ei) {
    int t = blockIdx.x * 256 + threadIdx.x;
    if (t >= N_EDGES / 4) return;
    int4 s4 = __ldg(reinterpret_cast<const int4*>(ei) + t);
    int4 d4 = __ldg(reinterpret_cast<const int4*>(ei + N_EDGES) + t);
    int ss[4] = {s4.x, s4.y, s4.z, s4.w};
    int dd[4] = {d4.x, d4.y, d4.z, d4.w};
    #pragma unroll
    for (int q = 0; q < 4; ++q) {
        unsigned s = (unsigned)ss[q], d = (unsigned)dd[q];
        if (s < (unsigned)N_NODES && d < (unsigned)N_NODES) {
            int pos = atomicAdd(&g_deg[d], 1);
            if (pos < MAXDEG) g_srcs[d * MAXDEG + pos] = (int)s;
        }
    }
}

// ---------------- gather: z[n] = h_fp32[n] + sum bf16 h[s] -----------------
__global__ __launch_bounds__(256, 6) void gather_kernel(
    const float* __restrict__ x, int in_sel)
{
    const float* __restrict__ hin = (in_sel < 0) ? x : g_h[in_sel];
    const __nv_bfloat16* __restrict__ hb = (in_sel < 0) ? g_xb : g_hb[in_sel];
    const float4* __restrict__ h4 = reinterpret_cast<const float4*>(hin);
    unsigned t = blockIdx.x * 256u + threadIdx.x;
    if (t >= (unsigned)N_NODES * 16u) return;
    unsigned n = t >> 4;
    unsigned c = t & 15u;

    float4 acc = __ldg(h4 + (size_t)n * 16 + c);   // self term (fp32)
    int deg = min(__ldg(&g_deg[n]), MAXDEG);
    const int4* __restrict__ sp4 = reinterpret_cast<const int4*>(g_srcs + (size_t)n * MAXDEG);

    int e = 0;
    for (; e + 4 <= deg; e += 4) {
        int4 s = __ldg(sp4 + (e >> 2));
        unsigned long long r0 = __ldg(reinterpret_cast<const unsigned long long*>(
            hb + (size_t)s.x * D + c * 4));
        unsigned long long r1 = __ldg(reinterpret_cast<const unsigned long long*>(
            hb + (size_t)s.y * D + c * 4));
        unsigned long long r2 = __ldg(reinterpret_cast<const unsigned long long*>(
            hb + (size_t)s.z * D + c * 4));
        unsigned long long r3 = __ldg(reinterpret_cast<const unsigned long long*>(
            hb + (size_t)s.w * D + c * 4));
        acc_bf4(acc, r0); acc_bf4(acc, r1); acc_bf4(acc, r2); acc_bf4(acc, r3);
    }
    const int* __restrict__ sp = g_srcs + (size_t)n * MAXDEG;
    for (; e < deg; ++e) {
        int s = __ldg(sp + e);
        unsigned long long r = __ldg(reinterpret_cast<const unsigned long long*>(
            hb + (size_t)s * D + c * 4));
        acc_bf4(acc, r);
    }
    reinterpret_cast<float4*>(g_z)[(size_t)n * 16 + c] = acc;
}

// ---------------- MLP kernel (round-15 core) + optional fused pool ---------
// 8 nodes x 4 outs tile, 256 threads, 4 blocks/SM. When do_pool=1 (last
// layer), zt is reused after GEMM2 as a per-block [16][64] pool accumulator:
// smem atomics collect outputs, then <=2x64 global atomics flush per block.
#define ZT_LD 132
#define MLP_SMEM_FLOATS (D * ZT_LD + D * D + 4 * D)  // 12800 floats = 51.2KB

__global__ __launch_bounds__(256, 4) void mlp_kernel(
    int out_sel, int layer, int write_bf16, int do_pool,
    const int* __restrict__ bat,
    const float* __restrict__ W1, const float* __restrict__ b1,
    const float* __restrict__ g1, const float* __restrict__ be1,
    const float* __restrict__ m1, const float* __restrict__ v1,
    const float* __restrict__ W2, const float* __restrict__ b2,
    const float* __restrict__ g2, const float* __restrict__ be2,
    const float* __restrict__ m2, const float* __restrict__ v2)
{
    extern __shared__ float smem[];
    float* zt  = smem;                    // [64][132] transposed activations
    float* Wb  = smem + D * ZT_LD;        // [64][64] current weight
    float* sc1 = Wb + D * D;
    float* sh1 = sc1 + D;
    float* sc2 = sh1 + D;
    float* sh2 = sc2 + D;

    const int tid = threadIdx.x;
    const int node0 = blockIdx.x * NPB;
    float* __restrict__ hout = g_h[out_sel];
    __nv_bfloat16* __restrict__ hbout = g_hb[out_sel];
    const float4* __restrict__ z4 = reinterpret_cast<const float4*>(g_z);

    // stage W1 + folded BN params
    const float* w1 = W1 + layer * D * D;
    #pragma unroll
    for (int i = tid; i < D * D; i += 256) Wb[i] = __ldg(w1 + i);
    if (tid < D) {
        int o = layer * D + tid;
        float s1 = __ldg(g1 + o) * rsqrtf(__ldg(v1 + o) + BN_EPS);
        sc1[tid] = s1;
        sh1[tid] = (__ldg(b1 + o) - __ldg(m1 + o)) * s1 + __ldg(be1 + o);
        float s2 = __ldg(g2 + o) * rsqrtf(__ldg(v2 + o) + BN_EPS);
        sc2[tid] = s2;
        sh2[tid] = (__ldg(b2 + o) - __ldg(m2 + o)) * s2 + __ldg(be2 + o);
    }

    // stage z transposed: task = (local node, chunk)
    #pragma unroll
    for (int it = 0; it < (NPB * 16) / 256; ++it) {
        int task = tid + it * 256;
        int nl = task >> 4;
        int c  = task & 15;
        int n  = node0 + nl;
        if (n < N_NODES) {
            float4 v = __ldg(z4 + (size_t)n * 16 + c);
            int k = c * 4;
            zt[(k + 0) * ZT_LD + nl] = v.x;
            zt[(k + 1) * ZT_LD + nl] = v.y;
            zt[(k + 2) * ZT_LD + nl] = v.z;
            zt[(k + 3) * ZT_LD + nl] = v.w;
        }
    }
    __syncthreads();

    // ---- GEMM thread tile: 8 nodes (4 f32x2 pairs) x 4 outs ----
    const int tj = tid & 15;
    const int tn = tid >> 4;
    const int j0 = tj * 4;
    const int n0 = tn * 8;

    unsigned long long acc[4][4];
    #pragma unroll
    for (int p = 0; p < 4; ++p)
        #pragma unroll
        for (int j = 0; j < 4; ++j) acc[p][j] = 0ull;

    // GEMM1: z @ W1
    #pragma unroll 4
    for (int k = 0; k < D; ++k) {
        ulonglong2 za = *reinterpret_cast<const ulonglong2*>(zt + k * ZT_LD + n0);
        ulonglong2 zb = *reinterpret_cast<const ulonglong2*>(zt + k * ZT_LD + n0 + 4);
        float4 w = *reinterpret_cast<const float4*>(Wb + k * D + j0);
        unsigned long long wd0 = pack2(w.x, w.x), wd1 = pack2(w.y, w.y);
        unsigned long long wd2 = pack2(w.z, w.z), wd3 = pack2(w.w, w.w);
        fma2(acc[0][0], za.x, wd0); fma2(acc[0][1], za.x, wd1);
        fma2(acc[0][2], za.x, wd2); fma2(acc[0][3], za.x, wd3);
        fma2(acc[1][0], za.y, wd0); fma2(acc[1][1], za.y, wd1);
        fma2(acc[1][2], za.y, wd2); fma2(acc[1][3], za.y, wd3);
        fma2(acc[2][0], zb.x, wd0); fma2(acc[2][1], zb.x, wd1);
        fma2(acc[2][2], zb.x, wd2); fma2(acc[2][3], zb.x, wd3);
        fma2(acc[3][0], zb.y, wd0); fma2(acc[3][1], zb.y, wd1);
        fma2(acc[3][2], zb.y, wd2); fma2(acc[3][3], zb.y, wd3);
    }
    __syncthreads();

    // BN1 + ReLU -> y back into zt (packed 8B stores); swap W2 into Wb
    {
        float s_[4] = {sc1[j0], sc1[j0 + 1], sc1[j0 + 2], sc1[j0 + 3]};
        float t_[4] = {sh1[j0], sh1[j0 + 1], sh1[j0 + 2], sh1[j0 + 3]};
        #pragma unroll
        for (int p = 0; p < 4; ++p)
            #pragma unroll
            for (int j = 0; j < 4; ++j) {
                float lo, hi;
                unpack2(lo, hi, acc[p][j]);
                lo = fmaxf(fmaf(lo, s_[j], t_[j]), 0.f);
                hi = fmaxf(fmaf(hi, s_[j], t_[j]), 0.f);
                *reinterpret_cast<unsigned long long*>(
                    zt + (j0 + j) * ZT_LD + n0 + 2 * p) = pack2(lo, hi);
            }
    }
    const float* w2 = W2 + layer * D * D;
    #pragma unroll
    for (int i = tid; i < D * D; i += 256) Wb[i] = __ldg(w2 + i);
    __syncthreads();

    // GEMM2: y @ W2
    #pragma unroll
    for (int p = 0; p < 4; ++p)
        #pragma unroll
        for (int j = 0; j < 4; ++j) acc[p][j] = 0ull;

    #pragma unroll 4
    for (int k = 0; k < D; ++k) {
        ulonglong2 ya = *reinterpret_cast<const ulonglong2*>(zt + k * ZT_LD + n0);
        ulonglong2 yb = *reinterpret_cast<const ulonglong2*>(zt + k * ZT_LD + n0 + 4);
        float4 w = *reinterpret_cast<const float4*>(Wb + k * D + j0);
        unsigned long long wd0 = pack2(w.x, w.x), wd1 = pack2(w.y, w.y);
        unsigned long long wd2 = pack2(w.z, w.z), wd3 = pack2(w.w, w.w);
        fma2(acc[0][0], ya.x, wd0); fma2(acc[0][1], ya.x, wd1);
        fma2(acc[0][2], ya.x, wd2); fma2(acc[0][3], ya.x, wd3);
        fma2(acc[1][0], ya.y, wd0); fma2(acc[1][1], ya.y, wd1);
        fma2(acc[1][2], ya.y, wd2); fma2(acc[1][3], ya.y, wd3);
        fma2(acc[2][0], yb.x, wd0); fma2(acc[2][1], yb.x, wd1);
        fma2(acc[2][2], yb.x, wd2); fma2(acc[2][3], yb.x, wd3);
        fma2(acc[3][0], yb.y, wd0); fma2(acc[3][1], yb.y, wd1);
        fma2(acc[3][2], yb.y, wd2); fma2(acc[3][3], yb.y, wd3);
    }

    // fused-pool prep: zt is dead after GEMM2; reuse as pool accumulator
    float* pacc = zt;                 // [<=16][64]
    float* scnt = zt + N_GRAPHS * D;  // [<=16]
    int bmin = 0, span = 0;
    if (do_pool) {
        __syncthreads();              // all zt reads of GEMM2 done
        bmin = __ldg(bat + min(node0, N_NODES - 1));
        int bmax = __ldg(bat + min(node0 + NPB - 1, N_NODES - 1));
        span = bmax - bmin + 1;
        for (int i = tid; i < span * D; i += 256) pacc[i] = 0.f;
        if (tid < span) scnt[tid] = 0.f;
        __syncthreads();
    }

    // BN2 + ReLU, stores + optional bf16 mirror + optional pool accumulate
    {
        float s_[4] = {sc2[j0], sc2[j0 + 1], sc2[j0 + 2], sc2[j0 + 3]};
        float t_[4] = {sh2[j0], sh2[j0 + 1], sh2[j0 + 2], sh2[j0 + 3]};
        #pragma unroll
        for (int p = 0; p < 4; ++p) {
            float lo[4], hi[4];
            #pragma unroll
            for (int j = 0; j < 4; ++j) {
                float a, b;
                unpack2(a, b, acc[p][j]);
                lo[j] = fmaxf(fmaf(a, s_[j], t_[j]), 0.f);
                hi[j] = fmaxf(fmaf(b, s_[j], t_[j]), 0.f);
            }
            int na = node0 + n0 + 2 * p;
            int nb = na + 1;
            if (na < N_NODES) {
                *reinterpret_cast<float4*>(hout + (size_t)na * D + j0) =
                    make_float4(lo[0], lo[1], lo[2], lo[3]);
                if (write_bf16) {
                    __nv_bfloat162 r[2];
                    r[0] = __floats2bfloat162_rn(lo[0], lo[1]);
                    r[1] = __floats2bfloat162_rn(lo[2], lo[3]);
                    *reinterpret_cast<unsigned long long*>(hbout + (size_t)na * D + j0) =
                        *reinterpret_cast<unsigned long long*>(r);
                }
                if (do_pool) {
                    int ba = __ldg(bat + na) - bmin;
                    float* row = pacc + ba * D + j0;
                    atomicAdd(row + 0, lo[0]); atomicAdd(row + 1, lo[1]);
                    atomicAdd(row + 2, lo[2]); atomicAdd(row + 3, lo[3]);
                    if (tj == 0) atomicAdd(&scnt[ba], 1.f);
                }
            }
            if (nb < N_NODES) {
                *reinterpret_cast<float4*>(hout + (size_t)nb * D + j0) =
                    make_float4(hi[0], hi[1], hi[2], hi[3]);
                if (write_bf16) {
                    __nv_bfloat162 r[2];
                    r[0] = __floats2bfloat162_rn(hi[0], hi[1]);
                    r[1] = __floats2bfloat162_rn(hi[2], hi[3]);
                    *reinterpret_cast<unsigned long long*>(hbout + (size_t)nb * D + j0) =
                        *reinterpret_cast<unsigned long long*>(r);
                }
                if (do_pool) {
                    int bb = __ldg(bat + nb) - bmin;
                    float* row = pacc + bb * D + j0;
                    atomicAdd(row + 0, hi[0]); atomicAdd(row + 1, hi[1]);
                    atomicAdd(row + 2, hi[2]); atomicAdd(row + 3, hi[3]);
                    if (tj == 0) atomicAdd(&scnt[bb], 1.f);
                }
            }
        }
    }

    // flush block-local pool sums (span is 1-2 for sorted batch)
    if (do_pool) {
        __syncthreads();
        for (int g = 0; g < span; ++g) {
            if (tid < D) atomicAdd(&g_pool[(bmin + g) * D + tid], pacc[g * D + tid]);
            else if (tid == D) atomicAdd(&g_cnt[bmin + g], scnt[g]);
        }
    }
}

// ---------------- heads: out = [primary(16x6), secondary(16x6)] ----------------
__global__ void head_kernel(const float* __restrict__ wp, const float* __restrict__ bp,
                            const float* __restrict__ ws, const float* __restrict__ bs,
                            float* __restrict__ out) {
    int t = threadIdx.x;
    if (t >= N_GRAPHS * N_CLASSES) return;
    int g = t / N_CLASSES, c = t % N_CLASSES;
    float inv = 1.f / fmaxf(g_cnt[g], 1.f);
    float accP = 0.f, accS = 0.f;
    #pragma unroll
    for (int d = 0; d < D; ++d) {
        float p = g_pool[g * D + d] * inv;
        accP = fmaf(p, wp[d * N_CLASSES + c], accP);
        accS = fmaf(p, ws[d * N_CLASSES + c], accS);
    }
    out[g * N_CLASSES + c] = accP + bp[c];
    out[N_GRAPHS * N_CLASSES + g * N_CLASSES + c] = accS + bs[c];
}

// ---------------- launch ----------------
extern "C" void kernel_launch(void* const* d_in, const int* in_sizes, int n_in,
                              void* d_out, int out_size) {
    const float* x   = (const float*)d_in[0];
    const int*   ei  = (const int*)d_in[1];    // int32 (JAX x64 disabled)
    const int*   bat = (const int*)d_in[2];    // int32
    const float* W1  = (const float*)d_in[3];
    const float* b1  = (const float*)d_in[4];
    const float* g1  = (const float*)d_in[5];
    const float* be1 = (const float*)d_in[6];
    const float* m1  = (const float*)d_in[7];
    const float* v1  = (const float*)d_in[8];
    const float* W2  = (const float*)d_in[9];
    const float* b2  = (const float*)d_in[10];
    const float* g2  = (const float*)d_in[11];
    const float* be2 = (const float*)d_in[12];
    const float* m2  = (const float*)d_in[13];
    const float* v2  = (const float*)d_in[14];
    const float* wp  = (const float*)d_in[15];
    const float* bp  = (const float*)d_in[16];
    const float* ws  = (const float*)d_in[17];
    const float* bs  = (const float*)d_in[18];
    float* out = (float*)d_out;

    const size_t mlp_smem = MLP_SMEM_FLOATS * sizeof(float);  // 51.2 KB
    cudaFuncSetAttribute(mlp_kernel, cudaFuncAttributeMaxDynamicSharedMemorySize,
                         (int)mlp_smem);

    // prep (zeros + bf16 mirror of x) + padded CSR
    prep_kernel<<<512, 256>>>(x);
    place_kernel<<<(N_EDGES / 4 + 255) / 256, 256>>>(ei);

    const int gather_grid = (N_NODES * 16 + 255) / 256;
    const int mlp_grid = (N_NODES + NPB - 1) / NPB;

    gather_kernel<<<gather_grid, 256>>>(x, -1);
    mlp_kernel<<<mlp_grid, 256, mlp_smem>>>(0, 0, 1, 0, bat,
        W1, b1, g1, be1, m1, v1, W2, b2, g2, be2, m2, v2);
    gather_kernel<<<gather_grid, 256>>>(x, 0);
    mlp_kernel<<<mlp_grid, 256, mlp_smem>>>(1, 1, 1, 0, bat,
        W1, b1, g1, be1, m1, v1, W2, b2, g2, be2, m2, v2);
    gather_kernel<<<gather_grid, 256>>>(x, 1);
    mlp_kernel<<<mlp_grid, 256, mlp_smem>>>(0, 2, 0, 1, bat,   // fused pool
        W1, b1, g1, be1, m1, v1, W2, b2, g2, be2, m2, v2);

    head_kernel<<<1, 128>>>(wp, bp, ws, bs, out);
}